// round 15
// baseline (speedup 1.0000x reference)
#include <cuda_runtime.h>
#include <cuda_fp16.h>
#include <cstdint>

#define Bb 4
#define Cc 256
#define Nn 4096
#define Gg 8
#define CPG 32
#define GSIZE (CPG*Nn)
#define EPSf 1e-5f

// ---- fp16 arena (halfs) ----
#define OFF_XN16   ((size_t)0)
#define OFF_QKV16  (OFF_XN16  + (size_t)Bb*Cc*Nn)
#define OFF_P16    (OFF_QKV16 + (size_t)Bb*3*Cc*Nn)
#define OFF_AO16   (OFF_P16   + (size_t)Bb*Nn*Nn)
#define OFF_WQ16   (OFF_AO16  + (size_t)Bb*Cc*Nn)
#define OFF_WO16   (OFF_WQ16  + (size_t)Cc*3*Cc)
#define H_SZ       (OFF_WO16  + (size_t)Cc*Cc)

__device__ __align__(16) __half g_h[H_SZ];
__device__ float g_stats[Bb*Gg*2];

// ============================================================
// PTX macros
// ============================================================
#define CPA16(smem_u32, gptr) \
    asm volatile("cp.async.cg.shared.global [%0], [%1], 16;" \
                 :: "r"(smem_u32), "l"(gptr))
#define CP_COMMIT() asm volatile("cp.async.commit_group;")
#define CP_WAIT(n)  asm volatile("cp.async.wait_group %0;" :: "n"(n))

#define LDSM4T(R, addr) \
    asm volatile("ldmatrix.sync.aligned.m8n8.x4.trans.shared.b16 {%0,%1,%2,%3}, [%4];" \
        : "=r"((R)[0]), "=r"((R)[1]), "=r"((R)[2]), "=r"((R)[3]) : "r"(addr))
#define LDSM4N(R, addr) \
    asm volatile("ldmatrix.sync.aligned.m8n8.x4.shared.b16 {%0,%1,%2,%3}, [%4];" \
        : "=r"((R)[0]), "=r"((R)[1]), "=r"((R)[2]), "=r"((R)[3]) : "r"(addr))

#define MMA16(C, A, B) \
    asm volatile( \
        "mma.sync.aligned.m16n8k16.row.col.f32.f16.f16.f32 " \
        "{%0,%1,%2,%3},{%4,%5,%6,%7},{%8,%9},{%0,%1,%2,%3};" \
        : "+f"((C)[0]), "+f"((C)[1]), "+f"((C)[2]), "+f"((C)[3]) \
        : "r"((A)[0]), "r"((A)[1]), "r"((A)[2]), "r"((A)[3]), \
          "r"((B)[0]), "r"((B)[1]))

// ============================================================
// GroupNorm, 3 passes
// ============================================================
__global__ void gn_zero() {
    if (threadIdx.x < Bb * Gg * 2) g_stats[threadIdx.x] = 0.f;
}

__global__ void gn_part(const float* __restrict__ x) {
    int bg = blockIdx.x >> 3, sl = blockIdx.x & 7;
    const float4* xp = (const float4*)(x + (size_t)bg * GSIZE + (size_t)sl * (GSIZE / 8));
    const int n4 = GSIZE / 8 / 4;
    float s = 0.f, ss = 0.f;
    for (int i = threadIdx.x; i < n4; i += blockDim.x) {
        float4 v = xp[i];
        s  += v.x + v.y + v.z + v.w;
        ss += v.x * v.x + v.y * v.y + v.z * v.z + v.w * v.w;
    }
    __shared__ float sh_s[8], sh_ss[8];
    int wid = threadIdx.x >> 5, lid = threadIdx.x & 31;
    #pragma unroll
    for (int o = 16; o; o >>= 1) {
        s  += __shfl_down_sync(0xffffffffu, s,  o);
        ss += __shfl_down_sync(0xffffffffu, ss, o);
    }
    if (lid == 0) { sh_s[wid] = s; sh_ss[wid] = ss; }
    __syncthreads();
    if (threadIdx.x == 0) {
        float ts = 0.f, tss = 0.f;
        #pragma unroll
        for (int w = 0; w < 8; w++) { ts += sh_s[w]; tss += sh_ss[w]; }
        atomicAdd(&g_stats[bg * 2], ts);
        atomicAdd(&g_stats[bg * 2 + 1], tss);
    }
}

__global__ void gn_apply(const float* __restrict__ x,
                         const float* __restrict__ gamma,
                         const float* __restrict__ beta) {
    const size_t total4 = (size_t)Bb * Cc * Nn / 4;
    size_t stride = (size_t)gridDim.x * blockDim.x;
    for (size_t i4 = (size_t)blockIdx.x * blockDim.x + threadIdx.x;
         i4 < total4; i4 += stride) {
        size_t idx = i4 * 4;
        int c_glob = (int)(idx / Nn);
        int c = c_glob % Cc;
        int bg = (c_glob / Cc) * Gg + c / CPG;
        float mean = g_stats[bg * 2] * (1.0f / GSIZE);
        float var  = g_stats[bg * 2 + 1] * (1.0f / GSIZE) - mean * mean;
        float rstd = rsqrtf(var + EPSf);
        float gm = gamma[c] * rstd, bt = beta[c] - mean * rstd * gamma[c];
        float4 v = *(const float4*)(x + idx);
        *(__half2*)(g_h + OFF_XN16 + idx)     = __floats2half2_rn(v.x * gm + bt, v.y * gm + bt);
        *(__half2*)(g_h + OFF_XN16 + idx + 2) = __floats2half2_rn(v.z * gm + bt, v.w * gm + bt);
    }
}

// ============================================================
// transpose fp32 ext [M][K] -> fp16 arena [K][M]
// ============================================================
__global__ void tr_f2h(const float* __restrict__ in, size_t outOff, int M, int K) {
    __shared__ float t[32][33];
    int k0 = blockIdx.x * 32, m0 = blockIdx.y * 32;
    int tx = threadIdx.x, ty = threadIdx.y;
    #pragma unroll
    for (int i = ty; i < 32; i += 8)
        t[i][tx] = in[(size_t)(m0 + i) * K + k0 + tx];
    __syncthreads();
    __half* op = g_h + outOff;
    #pragma unroll
    for (int i = ty; i < 32; i += 8)
        op[(size_t)(k0 + i) * M + m0 + tx] = __float2half(t[tx][i]);
}

// ============================================================
// gemm_big: fp16 GEMM, CTA 128x256, 8 warps of 64x64.
//   C[m][n] = sum_k At[k][m]*B[k][n]; A-trans [k][m], B [k][n].
//   3-stage x 32k pipeline, 2 subchunks/iter.
//   modes: 0 fp16+bias; 1 fp16*scale
// ============================================================
#define HLD 136
#define BLD 264
#define STG_B (32*HLD + 32*BLD)        // halfs per stage = 12800
#define SMEM_B_BYTES (3*STG_B*2)       // 76800

#define B_LOAD(buf, kk) do {                                                   \
    uint32_t sa_ = smb + (uint32_t)((buf) * STG_B) * 2;                        \
    uint32_t sb_ = sa_ + (uint32_t)(32 * HLD) * 2;                             \
    { int id_ = tid;       int k_ = id_ >> 4, q_ = id_ & 15;                   \
      CPA16(sa_ + (uint32_t)(k_ * HLD + q_ * 8) * 2,                           \
            Ap + (size_t)((kk) + k_) * M + bm + q_ * 8);                       \
      CPA16(sa_ + (uint32_t)((k_ + 16) * HLD + q_ * 8) * 2,                    \
            Ap + (size_t)((kk) + k_ + 16) * M + bm + q_ * 8); }                \
    { int id_ = tid;       int k_ = id_ >> 5, q_ = id_ & 31;                   \
      CPA16(sb_ + (uint32_t)(k_ * BLD + q_ * 8) * 2,                           \
            Bp + (size_t)((kk) + k_) * N + bn + q_ * 8);                       \
      CPA16(sb_ + (uint32_t)((k_ + 8) * BLD + q_ * 8) * 2,                     \
            Bp + (size_t)((kk) + k_ + 8) * N + bn + q_ * 8);                   \
      CPA16(sb_ + (uint32_t)((k_ + 16) * BLD + q_ * 8) * 2,                    \
            Bp + (size_t)((kk) + k_ + 16) * N + bn + q_ * 8);                  \
      CPA16(sb_ + (uint32_t)((k_ + 24) * BLD + q_ * 8) * 2,                    \
            Bp + (size_t)((kk) + k_ + 24) * N + bn + q_ * 8); }                \
    CP_COMMIT();                                                               \
} while (0)

__global__ __launch_bounds__(256) void gemm_big(
    size_t aOff, size_t bOff, size_t cOff,
    int M, int N, int K,
    size_t sA, size_t sB, size_t sC,
    const float* __restrict__ bias,
    float scale, int mode)
{
    extern __shared__ __half sm[];
    uint32_t smb = (uint32_t)__cvta_generic_to_shared(sm);

    int bz = blockIdx.z;
    const __half* Ap = g_h + aOff + (size_t)bz * sA;
    const __half* Bp = g_h + bOff + (size_t)bz * sB;
    __half* Cp = g_h + cOff + (size_t)bz * sC;
    int bm = blockIdx.y * 128, bn = blockIdx.x * 256;
    int tid = threadIdx.x, lane = tid & 31, wid = tid >> 5;
    int wm = (wid & 1) * 64, wn = (wid >> 1) * 64;

    float acc[4][8][4];
    #pragma unroll
    for (int i = 0; i < 4; i++)
        #pragma unroll
        for (int j = 0; j < 8; j++)
            #pragma unroll
            for (int r = 0; r < 4; r++) acc[i][j][r] = 0.f;

    int aRow = ((lane >> 4) << 3) + (lane & 7);
    int aCol = ((lane >> 3) & 1) * 8;
    int bRow = ((lane >> 3) & 1) * 8 + (lane & 7);
    int bCol = (lane >> 4) * 8;

    int steps = K / 32;
    B_LOAD(0, 0); B_LOAD(1, 32);

    for (int it = 0; it < steps; it++) {
        CP_WAIT(1);
        __syncthreads();
        if (it + 2 < steps) { B_LOAD((it + 2) % 3, (it + 2) * 32); }
        else                { CP_COMMIT(); }

        uint32_t sa = smb + (uint32_t)((it % 3) * STG_B) * 2;
        uint32_t sb = sa + (uint32_t)(32 * HLD) * 2;

        #pragma unroll
        for (int sc = 0; sc < 2; sc++) {
            uint32_t a[4][4], b[8][2];
            #pragma unroll
            for (int mt = 0; mt < 4; mt++) {
                uint32_t ad = sa + (uint32_t)((sc * 16 + aRow) * HLD + wm + mt * 16 + aCol) * 2;
                LDSM4T(a[mt], ad);
            }
            #pragma unroll
            for (int np = 0; np < 4; np++) {
                uint32_t bd = sb + (uint32_t)((sc * 16 + bRow) * BLD + wn + np * 16 + bCol) * 2;
                uint32_t rr[4];
                LDSM4T(rr, bd);
                b[np * 2][0] = rr[0]; b[np * 2][1] = rr[1];
                b[np * 2 + 1][0] = rr[2]; b[np * 2 + 1][1] = rr[3];
            }
            #pragma unroll
            for (int mt = 0; mt < 4; mt++)
                #pragma unroll
                for (int nt = 0; nt < 8; nt++)
                    MMA16(acc[mt][nt], a[mt], b[nt]);
        }
    }

    #pragma unroll
    for (int mt = 0; mt < 4; mt++) {
        int r0 = bm + wm + mt * 16 + (lane >> 2);
        float b0f = (mode == 0 && bias) ? bias[r0] : 0.f;
        float b1f = (mode == 0 && bias) ? bias[r0 + 8] : 0.f;
        #pragma unroll
        for (int nt = 0; nt < 8; nt++) {
            int cc = bn + wn + nt * 8 + 2 * (lane & 3);
            float v0 = acc[mt][nt][0], v1 = acc[mt][nt][1];
            float v2 = acc[mt][nt][2], v3 = acc[mt][nt][3];
            if (mode == 0) {
                *(__half2*)&Cp[(size_t)r0 * N + cc] =
                    __floats2half2_rn(v0 + b0f, v1 + b0f);
                *(__half2*)&Cp[(size_t)(r0 + 8) * N + cc] =
                    __floats2half2_rn(v2 + b1f, v3 + b1f);
            } else {
                *(__half2*)&Cp[(size_t)r0 * N + cc] =
                    __floats2half2_rn(v0 * scale, v1 * scale);
                *(__half2*)&Cp[(size_t)(r0 + 8) * N + cc] =
                    __floats2half2_rn(v2 * scale, v3 * scale);
            }
        }
    }
}

// ============================================================
// gemm_h: 128x128, 8 warps of 64x32 (R11-proven). mode 2 only:
//   out fp32 ext = A*B + bias + residual
// ============================================================
#define BM 128
#define BN 128
#define STG_H (2*32*HLD)
#define SMEM_H_BYTES (4*STG_H*2)

#define H_LOAD(buf, kk) do {                                                   \
    uint32_t sa_ = smb + (uint32_t)((buf) * STG_H) * 2;                        \
    uint32_t sb_ = sa_ + (uint32_t)(32 * HLD) * 2;                             \
    int k_ = tid >> 4, q_ = tid & 15;                                          \
    CPA16(sa_ + (uint32_t)(k_ * HLD + q_ * 8) * 2,                             \
          Ap + (size_t)((kk) + k_) * M + bm + q_ * 8);                         \
    CPA16(sa_ + (uint32_t)((k_ + 16) * HLD + q_ * 8) * 2,                      \
          Ap + (size_t)((kk) + k_ + 16) * M + bm + q_ * 8);                    \
    CPA16(sb_ + (uint32_t)(k_ * HLD + q_ * 8) * 2,                             \
          Bp + (size_t)((kk) + k_) * N + bn + q_ * 8);                         \
    CPA16(sb_ + (uint32_t)((k_ + 16) * HLD + q_ * 8) * 2,                      \
          Bp + (size_t)((kk) + k_ + 16) * N + bn + q_ * 8);                    \
    CP_COMMIT();                                                               \
} while (0)

__global__ __launch_bounds__(256, 2) void gemm_h(
    size_t aOff, size_t bOff, float* Cext,
    int M, int N, int K,
    size_t sA, size_t sB, size_t sC,
    const float* __restrict__ bias,
    const float* __restrict__ resExt, size_t sRes)
{
    extern __shared__ __half sm[];
    uint32_t smb = (uint32_t)__cvta_generic_to_shared(sm);

    int bz = blockIdx.z;
    const __half* Ap = g_h + aOff + (size_t)bz * sA;
    const __half* Bp = g_h + bOff + (size_t)bz * sB;
    int bm = blockIdx.y * BM, bn = blockIdx.x * BN;
    int tid = threadIdx.x, lane = tid & 31, wid = tid >> 5;
    int wm = (wid & 1) * 64, wn = (wid >> 1) * 32;

    float acc[4][4][4];
    #pragma unroll
    for (int i = 0; i < 4; i++)
        #pragma unroll
        for (int j = 0; j < 4; j++)
            #pragma unroll
            for (int r = 0; r < 4; r++) acc[i][j][r] = 0.f;

    int aRow = ((lane >> 4) << 3) + (lane & 7);
    int aCol = ((lane >> 3) & 1) * 8;
    int bRow = ((lane >> 3) & 1) * 8 + (lane & 7);
    int bCol = (lane >> 4) * 8;

    int steps = K / 32;
    H_LOAD(0, 0); H_LOAD(1, 32); H_LOAD(2, 64);

    for (int it = 0; it < steps; it++) {
        CP_WAIT(2);
        __syncthreads();
        if (it + 3 < steps) { H_LOAD((it + 3) & 3, (it + 3) * 32); }
        else                { CP_COMMIT(); }

        uint32_t sa = smb + (uint32_t)((it & 3) * STG_H) * 2;
        uint32_t sb = sa + (uint32_t)(32 * HLD) * 2;

        #pragma unroll
        for (int sc = 0; sc < 2; sc++) {
            uint32_t a[4][4], b[4][2];
            #pragma unroll
            for (int mt = 0; mt < 4; mt++) {
                uint32_t ad = sa + (uint32_t)((sc * 16 + aRow) * HLD + wm + mt * 16 + aCol) * 2;
                LDSM4T(a[mt], ad);
            }
            #pragma unroll
            for (int np = 0; np < 2; np++) {
                uint32_t bd = sb + (uint32_t)((sc * 16 + bRow) * HLD + wn + np * 16 + bCol) * 2;
                uint32_t rr[4];
                LDSM4T(rr, bd);
                b[np * 2][0] = rr[0]; b[np * 2][1] = rr[1];
                b[np * 2 + 1][0] = rr[2]; b[np * 2 + 1][1] = rr[3];
            }
            #pragma unroll
            for (int mt = 0; mt < 4; mt++)
                #pragma unroll
                for (int nt = 0; nt < 4; nt++)
                    MMA16(acc[mt][nt], a[mt], b[nt]);
        }
    }

    #pragma unroll
    for (int mt = 0; mt < 4; mt++) {
        int r0 = bm + wm + mt * 16 + (lane >> 2);
        float b0f = bias[r0];
        float b1f = bias[r0 + 8];
        #pragma unroll
        for (int nt = 0; nt < 4; nt++) {
            int cc = bn + wn + nt * 8 + 2 * (lane & 3);
            float* Cp = Cext + (size_t)bz * sC;
            const float* rp = resExt + (size_t)bz * sRes;
            float2 ra = *(const float2*)&rp[(size_t)r0 * N + cc];
            float2 rb = *(const float2*)&rp[(size_t)(r0 + 8) * N + cc];
            *(float2*)&Cp[(size_t)r0 * N + cc] =
                make_float2(acc[mt][nt][0] + b0f + ra.x, acc[mt][nt][1] + b0f + ra.y);
            *(float2*)&Cp[(size_t)(r0 + 8) * N + cc] =
                make_float2(acc[mt][nt][2] + b1f + rb.x, acc[mt][nt][3] + b1f + rb.y);
        }
    }
}

// ============================================================
// attn*V:  ao[c][i] = sum_j V[c][j] * P[i][j]  (R11-proven)
//   A = V [m=c][k=j] (non-trans), B = P [n=i][k=j] (non-trans)
//   4-stage x 32k, 2 subchunks/iter.
// ============================================================
#define PLD 40
#define STG_V (2*128*PLD)
#define SMEM_V_BYTES (4*STG_V*2)

#define AV_LOAD(buf, kk) do {                                                  \
    uint32_t sv_ = smb + (uint32_t)((buf) * STG_V) * 2;                        \
    uint32_t sp_ = sv_ + (uint32_t)(128 * PLD) * 2;                            \
    int r_ = tid >> 2, q_ = tid & 3;                                           \
    CPA16(sv_ + (uint32_t)(r_ * PLD + q_ * 8) * 2,                             \
          Vp + (size_t)(bm + r_) * Nn + (kk) + q_ * 8);                        \
    CPA16(sv_ + (uint32_t)((r_ + 64) * PLD + q_ * 8) * 2,                      \
          Vp + (size_t)(bm + r_ + 64) * Nn + (kk) + q_ * 8);                   \
    CPA16(sp_ + (uint32_t)(r_ * PLD + q_ * 8) * 2,                             \
          Pp + (size_t)(bn + r_) * Nn + (kk) + q_ * 8);                        \
    CPA16(sp_ + (uint32_t)((r_ + 64) * PLD + q_ * 8) * 2,                      \
          Pp + (size_t)(bn + r_ + 64) * Nn + (kk) + q_ * 8);                   \
    CP_COMMIT();                                                               \
} while (0)

__global__ __launch_bounds__(256, 2) void gemm_av_h() {
    extern __shared__ __half sm[];
    uint32_t smb = (uint32_t)__cvta_generic_to_shared(sm);

    int bz = blockIdx.z;
    const __half* Vp = g_h + OFF_QKV16 + (size_t)bz * 3 * Cc * Nn + (size_t)2 * Cc * Nn;
    const __half* Pp = g_h + OFF_P16 + (size_t)bz * Nn * Nn;
    __half* Cp = g_h + OFF_AO16 + (size_t)bz * Cc * Nn;
    int bm = blockIdx.y * BM, bn = blockIdx.x * BN;
    int tid = threadIdx.x, lane = tid & 31, wid = tid >> 5;
    int wm = (wid & 1) * 64, wn = (wid >> 1) * 32;

    float acc[4][4][4];
    #pragma unroll
    for (int i = 0; i < 4; i++)
        #pragma unroll
        for (int j = 0; j < 4; j++)
            #pragma unroll
            for (int r = 0; r < 4; r++) acc[i][j][r] = 0.f;

    int vRow = ((lane >> 3) & 1) * 8 + (lane & 7);
    int vCol = (lane >> 4) * 8;
    int pRow = (lane >> 4) * 8 + (lane & 7);
    int pCol = ((lane >> 3) & 1) * 8;

    int steps = Nn / 32;
    AV_LOAD(0, 0); AV_LOAD(1, 32); AV_LOAD(2, 64);

    for (int it = 0; it < steps; it++) {
        CP_WAIT(2);
        __syncthreads();
        if (it + 3 < steps) { AV_LOAD((it + 3) & 3, (it + 3) * 32); }
        else                { CP_COMMIT(); }

        uint32_t sv = smb + (uint32_t)((it & 3) * STG_V) * 2;
        uint32_t sp = sv + (uint32_t)(128 * PLD) * 2;

        #pragma unroll
        for (int sc = 0; sc < 2; sc++) {
            uint32_t a[4][4], b[4][2];
            #pragma unroll
            for (int mt = 0; mt < 4; mt++) {
                uint32_t ad = sv + (uint32_t)((wm + mt * 16 + vRow) * PLD + sc * 16 + vCol) * 2;
                LDSM4N(a[mt], ad);
            }
            #pragma unroll
            for (int np = 0; np < 2; np++) {
                uint32_t pd = sp + (uint32_t)((wn + np * 16 + pRow) * PLD + sc * 16 + pCol) * 2;
                uint32_t rr[4];
                LDSM4N(rr, pd);
                b[np * 2][0] = rr[0]; b[np * 2][1] = rr[1];
                b[np * 2 + 1][0] = rr[2]; b[np * 2 + 1][1] = rr[3];
            }
            #pragma unroll
            for (int mt = 0; mt < 4; mt++)
                #pragma unroll
                for (int nt = 0; nt < 4; nt++)
                    MMA16(acc[mt][nt], a[mt], b[nt]);
        }
    }

    #pragma unroll
    for (int mt = 0; mt < 4; mt++) {
        int r0 = bm + wm + mt * 16 + (lane >> 2);
        #pragma unroll
        for (int nt = 0; nt < 4; nt++) {
            int cc = bn + wn + nt * 8 + 2 * (lane & 3);
            *(__half2*)&Cp[(size_t)r0 * Nn + cc] =
                __floats2half2_rn(acc[mt][nt][0], acc[mt][nt][1]);
            *(__half2*)&Cp[(size_t)(r0 + 8) * Nn + cc] =
                __floats2half2_rn(acc[mt][nt][2], acc[mt][nt][3]);
        }
    }
}

// ============================================================
// Softmax fp16 in-place on P16 rows (length 4096).
// ============================================================
__global__ void softmax_kernel() {
    __half2* r = (__half2*)(g_h + OFF_P16 +
                            ((size_t)blockIdx.y * Nn + blockIdx.x) * Nn);
    float2 v[8];
    float mx = -3.4e38f;
    #pragma unroll
    for (int i = 0; i < 8; i++) {
        v[i] = __half22float2(r[threadIdx.x + i * 256]);
        mx = fmaxf(mx, fmaxf(v[i].x, v[i].y));
    }
    __shared__ float sh[8];
    int wid = threadIdx.x >> 5, lid = threadIdx.x & 31;
    #pragma unroll
    for (int o = 16; o; o >>= 1) mx = fmaxf(mx, __shfl_xor_sync(0xffffffffu, mx, o));
    if (lid == 0) sh[wid] = mx;
    __syncthreads();
    mx = sh[0];
    #pragma unroll
    for (int w = 1; w < 8; w++) mx = fmaxf(mx, sh[w]);

    float s = 0.f;
    #pragma unroll
    for (int i = 0; i < 8; i++) {
        v[i].x = __expf(v[i].x - mx);
        v[i].y = __expf(v[i].y - mx);
        s += v[i].x + v[i].y;
    }
    #pragma unroll
    for (int o = 16; o; o >>= 1) s += __shfl_xor_sync(0xffffffffu, s, o);
    __shared__ float shs[8];
    if (lid == 0) shs[wid] = s;
    __syncthreads();
    s = 0.f;
    #pragma unroll
    for (int w = 0; w < 8; w++) s += shs[w];
    float inv = 1.0f / s;
    #pragma unroll
    for (int i = 0; i < 8; i++)
        r[threadIdx.x + i * 256] = __floats2half2_rn(v[i].x * inv, v[i].y * inv);
}

// ============================================================
extern "C" void kernel_launch(void* const* d_in, const int* in_sizes, int n_in,
                              void* d_out, int out_size) {
    const float* x     = (const float*)d_in[0];
    const float* gamma = (const float*)d_in[1];
    const float* beta  = (const float*)d_in[2];
    const float* qkv_w = (const float*)d_in[3];
    const float* qkv_b = (const float*)d_in[4];
    const float* out_w = (const float*)d_in[5];
    const float* out_b = (const float*)d_in[6];
    float* out = (float*)d_out;

    static bool attr_set = false;
    if (!attr_set) {
        cudaFuncSetAttribute(gemm_big, cudaFuncAttributeMaxDynamicSharedMemorySize,
                             SMEM_B_BYTES);
        cudaFuncSetAttribute(gemm_h, cudaFuncAttributeMaxDynamicSharedMemorySize,
                             SMEM_H_BYTES);
        cudaFuncSetAttribute(gemm_av_h, cudaFuncAttributeMaxDynamicSharedMemorySize,
                             SMEM_V_BYTES);
        attr_set = true;
    }

    gn_zero<<<1, 64>>>();
    gn_part<<<Bb * Gg * 8, 256>>>(x);
    gn_apply<<<4096, 256>>>(x, gamma, beta);

    tr_f2h<<<dim3(Cc / 32, 3 * Cc / 32), dim3(32, 8)>>>(qkv_w, OFF_WQ16, 3 * Cc, Cc);
    tr_f2h<<<dim3(Cc / 32, Cc / 32), dim3(32, 8)>>>(out_w, OFF_WO16, Cc, Cc);

    // qkv16 = Wq16 * xn16 + b   (M=768, N=4096, K=256), 128x256 tiles
    gemm_big<<<dim3(Nn / 256, 3 * Cc / 128, Bb), 256, SMEM_B_BYTES>>>(
        OFF_WQ16, OFF_XN16, OFF_QKV16,
        3 * Cc, Nn, Cc,
        0, (size_t)Cc * Nn, (size_t)3 * Cc * Nn,
        qkv_b, 1.0f, 0);

    // S16 = (Q^T K)/16   (M=N=4096, K=256) -> fp16 at P16, 128x256 tiles
    gemm_big<<<dim3(Nn / 256, Nn / 128, Bb), 256, SMEM_B_BYTES>>>(
        OFF_QKV16, OFF_QKV16 + (size_t)Cc * Nn, OFF_P16,
        Nn, Nn, Cc,
        (size_t)3 * Cc * Nn, (size_t)3 * Cc * Nn, (size_t)Nn * Nn,
        nullptr, 0.0625f, 1);

    softmax_kernel<<<dim3(Nn, Bb), 256>>>();

    // ao16 = P16 * V     (M=256, N=4096, K=4096)
    gemm_av_h<<<dim3(Nn / BN, Cc / BM, Bb), 256, SMEM_V_BYTES>>>();

    // out = Wo16 * ao16 + b + x   (M=256, N=4096, K=256) -> fp32 ext
    gemm_h<<<dim3(Nn / BN, Cc / BM, Bb), 256, SMEM_H_BYTES>>>(
        OFF_WO16, OFF_AO16, out,
        Cc, Nn, Cc,
        0, (size_t)Cc * Nn, (size_t)Cc * Nn,
        out_b, x, (size_t)Cc * Nn);
}

// round 16
// speedup vs baseline: 1.1353x; 1.1353x over previous
#include <cuda_runtime.h>
#include <cuda_fp16.h>
#include <cstdint>

#define Bb 4
#define Cc 256
#define Nn 4096
#define Gg 8
#define CPG 32
#define GSIZE (CPG*Nn)
#define EPSf 1e-5f
#define ESHIFT 4.0f

// ---- fp16 arena (halfs) ----
#define OFF_XN16   ((size_t)0)
#define OFF_QKV16  (OFF_XN16  + (size_t)Bb*Cc*Nn)
#define OFF_P16    (OFF_QKV16 + (size_t)Bb*3*Cc*Nn)
#define OFF_AO16   (OFF_P16   + (size_t)Bb*Nn*Nn)
#define OFF_WQ16   (OFF_AO16  + (size_t)Bb*Cc*Nn)
#define OFF_WO16   (OFF_WQ16  + (size_t)Cc*3*Cc)
#define H_SZ       (OFF_WO16  + (size_t)Cc*Cc)

__device__ __align__(16) __half g_h[H_SZ];
__device__ float g_stats[Bb*Gg*2];
__device__ float g_Z[Bb*Nn];          // un-normalized softmax row sums

// ============================================================
// PTX macros
// ============================================================
#define CPA16(smem_u32, gptr) \
    asm volatile("cp.async.cg.shared.global [%0], [%1], 16;" \
                 :: "r"(smem_u32), "l"(gptr))
#define CP_COMMIT() asm volatile("cp.async.commit_group;")
#define CP_WAIT(n)  asm volatile("cp.async.wait_group %0;" :: "n"(n))

#define LDSM4T(R, addr) \
    asm volatile("ldmatrix.sync.aligned.m8n8.x4.trans.shared.b16 {%0,%1,%2,%3}, [%4];" \
        : "=r"((R)[0]), "=r"((R)[1]), "=r"((R)[2]), "=r"((R)[3]) : "r"(addr))
#define LDSM4N(R, addr) \
    asm volatile("ldmatrix.sync.aligned.m8n8.x4.shared.b16 {%0,%1,%2,%3}, [%4];" \
        : "=r"((R)[0]), "=r"((R)[1]), "=r"((R)[2]), "=r"((R)[3]) : "r"(addr))

#define MMA16(C, A, B) \
    asm volatile( \
        "mma.sync.aligned.m16n8k16.row.col.f32.f16.f16.f32 " \
        "{%0,%1,%2,%3},{%4,%5,%6,%7},{%8,%9},{%0,%1,%2,%3};" \
        : "+f"((C)[0]), "+f"((C)[1]), "+f"((C)[2]), "+f"((C)[3]) \
        : "r"((A)[0]), "r"((A)[1]), "r"((A)[2]), "r"((A)[3]), \
          "r"((B)[0]), "r"((B)[1]))

// ============================================================
// zero stats + Z
// ============================================================
__global__ void zero_kernel() {
    int i = blockIdx.x * blockDim.x + threadIdx.x;
    if (i < Bb * Gg * 2) g_stats[i] = 0.f;
    if (i < Bb * Nn) g_Z[i] = 0.f;
}

// ============================================================
// GroupNorm, 2 passes after zero
// ============================================================
__global__ void gn_part(const float* __restrict__ x) {
    int bg = blockIdx.x >> 3, sl = blockIdx.x & 7;
    const float4* xp = (const float4*)(x + (size_t)bg * GSIZE + (size_t)sl * (GSIZE / 8));
    const int n4 = GSIZE / 8 / 4;
    float s = 0.f, ss = 0.f;
    for (int i = threadIdx.x; i < n4; i += blockDim.x) {
        float4 v = xp[i];
        s  += v.x + v.y + v.z + v.w;
        ss += v.x * v.x + v.y * v.y + v.z * v.z + v.w * v.w;
    }
    __shared__ float sh_s[8], sh_ss[8];
    int wid = threadIdx.x >> 5, lid = threadIdx.x & 31;
    #pragma unroll
    for (int o = 16; o; o >>= 1) {
        s  += __shfl_down_sync(0xffffffffu, s,  o);
        ss += __shfl_down_sync(0xffffffffu, ss, o);
    }
    if (lid == 0) { sh_s[wid] = s; sh_ss[wid] = ss; }
    __syncthreads();
    if (threadIdx.x == 0) {
        float ts = 0.f, tss = 0.f;
        #pragma unroll
        for (int w = 0; w < 8; w++) { ts += sh_s[w]; tss += sh_ss[w]; }
        atomicAdd(&g_stats[bg * 2], ts);
        atomicAdd(&g_stats[bg * 2 + 1], tss);
    }
}

__global__ void gn_apply(const float* __restrict__ x,
                         const float* __restrict__ gamma,
                         const float* __restrict__ beta) {
    const size_t total4 = (size_t)Bb * Cc * Nn / 4;
    size_t stride = (size_t)gridDim.x * blockDim.x;
    for (size_t i4 = (size_t)blockIdx.x * blockDim.x + threadIdx.x;
         i4 < total4; i4 += stride) {
        size_t idx = i4 * 4;
        int c_glob = (int)(idx / Nn);
        int c = c_glob % Cc;
        int bg = (c_glob / Cc) * Gg + c / CPG;
        float mean = g_stats[bg * 2] * (1.0f / GSIZE);
        float var  = g_stats[bg * 2 + 1] * (1.0f / GSIZE) - mean * mean;
        float rstd = rsqrtf(var + EPSf);
        float gm = gamma[c] * rstd, bt = beta[c] - mean * rstd * gamma[c];
        float4 v = *(const float4*)(x + idx);
        *(__half2*)(g_h + OFF_XN16 + idx)     = __floats2half2_rn(v.x * gm + bt, v.y * gm + bt);
        *(__half2*)(g_h + OFF_XN16 + idx + 2) = __floats2half2_rn(v.z * gm + bt, v.w * gm + bt);
    }
}

// ============================================================
// transpose fp32 ext [M][K] -> fp16 arena [K][M]
// ============================================================
__global__ void tr_f2h(const float* __restrict__ in, size_t outOff, int M, int K) {
    __shared__ float t[32][33];
    int k0 = blockIdx.x * 32, m0 = blockIdx.y * 32;
    int tx = threadIdx.x, ty = threadIdx.y;
    #pragma unroll
    for (int i = ty; i < 32; i += 8)
        t[i][tx] = in[(size_t)(m0 + i) * K + k0 + tx];
    __syncthreads();
    __half* op = g_h + outOff;
    #pragma unroll
    for (int i = ty; i < 32; i += 8)
        op[(size_t)(k0 + i) * M + m0 + tx] = __float2half(t[tx][i]);
}

// ============================================================
// fp16 GEMM (A-trans [k][m], B-trans [k][n]) - R11 config
//   4-stage x 32k pipeline, CTA 128x128, 8 warps of 64x32.
//   modes: 0 fp16+bias; 1 fp16 E=exp(v*scale-4) + row-sum atomics;
//          2 fp32 ext +bias+res
// ============================================================
#define BM 128
#define BN 128
#define HLD 136
#define STG_H (2*32*HLD)
#define SMEM_H_BYTES (4*STG_H*2)

#define H_LOAD(buf, kk) do {                                                   \
    uint32_t sa_ = smb + (uint32_t)((buf) * STG_H) * 2;                        \
    uint32_t sb_ = sa_ + (uint32_t)(32 * HLD) * 2;                             \
    int k_ = tid >> 4, q_ = tid & 15;                                          \
    CPA16(sa_ + (uint32_t)(k_ * HLD + q_ * 8) * 2,                             \
          Ap + (size_t)((kk) + k_) * M + bm + q_ * 8);                         \
    CPA16(sa_ + (uint32_t)((k_ + 16) * HLD + q_ * 8) * 2,                      \
          Ap + (size_t)((kk) + k_ + 16) * M + bm + q_ * 8);                    \
    CPA16(sb_ + (uint32_t)(k_ * HLD + q_ * 8) * 2,                             \
          Bp + (size_t)((kk) + k_) * N + bn + q_ * 8);                         \
    CPA16(sb_ + (uint32_t)((k_ + 16) * HLD + q_ * 8) * 2,                      \
          Bp + (size_t)((kk) + k_ + 16) * N + bn + q_ * 8);                    \
    CP_COMMIT();                                                               \
} while (0)

__global__ __launch_bounds__(256, 2) void gemm_h(
    size_t aOff, size_t bOff, size_t cOff, float* Cext,
    int M, int N, int K,
    size_t sA, size_t sB, size_t sC,
    const float* __restrict__ bias,
    const float* __restrict__ resExt, size_t sRes,
    float scale, int mode)
{
    extern __shared__ __half sm[];
    uint32_t smb = (uint32_t)__cvta_generic_to_shared(sm);

    int bz = blockIdx.z;
    const __half* Ap = g_h + aOff + (size_t)bz * sA;
    const __half* Bp = g_h + bOff + (size_t)bz * sB;
    int bm = blockIdx.y * BM, bn = blockIdx.x * BN;
    int tid = threadIdx.x, lane = tid & 31, wid = tid >> 5;
    int wm = (wid & 1) * 64, wn = (wid >> 1) * 32;

    float acc[4][4][4];
    #pragma unroll
    for (int i = 0; i < 4; i++)
        #pragma unroll
        for (int j = 0; j < 4; j++)
            #pragma unroll
            for (int r = 0; r < 4; r++) acc[i][j][r] = 0.f;

    int aRow = ((lane >> 4) << 3) + (lane & 7);
    int aCol = ((lane >> 3) & 1) * 8;
    int bRow = ((lane >> 3) & 1) * 8 + (lane & 7);
    int bCol = (lane >> 4) * 8;

    int steps = K / 32;
    H_LOAD(0, 0); H_LOAD(1, 32); H_LOAD(2, 64);

    for (int it = 0; it < steps; it++) {
        CP_WAIT(2);
        __syncthreads();
        if (it + 3 < steps) { H_LOAD((it + 3) & 3, (it + 3) * 32); }
        else                { CP_COMMIT(); }

        uint32_t sa = smb + (uint32_t)((it & 3) * STG_H) * 2;
        uint32_t sb = sa + (uint32_t)(32 * HLD) * 2;

        #pragma unroll
        for (int sc = 0; sc < 2; sc++) {
            uint32_t a[4][4], b[4][2];
            #pragma unroll
            for (int mt = 0; mt < 4; mt++) {
                uint32_t ad = sa + (uint32_t)((sc * 16 + aRow) * HLD + wm + mt * 16 + aCol) * 2;
                LDSM4T(a[mt], ad);
            }
            #pragma unroll
            for (int np = 0; np < 2; np++) {
                uint32_t bd = sb + (uint32_t)((sc * 16 + bRow) * HLD + wn + np * 16 + bCol) * 2;
                uint32_t rr[4];
                LDSM4T(rr, bd);
                b[np * 2][0] = rr[0]; b[np * 2][1] = rr[1];
                b[np * 2 + 1][0] = rr[2]; b[np * 2 + 1][1] = rr[3];
            }
            #pragma unroll
            for (int mt = 0; mt < 4; mt++)
                #pragma unroll
                for (int nt = 0; nt < 4; nt++)
                    MMA16(acc[mt][nt], a[mt], b[nt]);
        }
    }

    // epilogue
    #pragma unroll
    for (int mt = 0; mt < 4; mt++) {
        int r0 = bm + wm + mt * 16 + (lane >> 2);
        float b0f = (mode == 0 && bias) ? bias[r0] : 0.f;
        float b1f = (mode == 0 && bias) ? bias[r0 + 8] : 0.f;
        float rs0 = 0.f, rs1 = 0.f;    // row sums for mode 1
        #pragma unroll
        for (int nt = 0; nt < 4; nt++) {
            int cc = bn + wn + nt * 8 + 2 * (lane & 3);
            float v0 = acc[mt][nt][0], v1 = acc[mt][nt][1];
            float v2 = acc[mt][nt][2], v3 = acc[mt][nt][3];
            if (mode == 0) {
                __half* Ch = g_h + cOff + (size_t)bz * sC;
                *(__half2*)&Ch[(size_t)r0 * N + cc] =
                    __floats2half2_rn(v0 + b0f, v1 + b0f);
                *(__half2*)&Ch[(size_t)(r0 + 8) * N + cc] =
                    __floats2half2_rn(v2 + b1f, v3 + b1f);
            } else if (mode == 1) {
                __half* Ch = g_h + cOff + (size_t)bz * sC;
                float e0 = __expf(v0 * scale - ESHIFT);
                float e1 = __expf(v1 * scale - ESHIFT);
                float e2 = __expf(v2 * scale - ESHIFT);
                float e3 = __expf(v3 * scale - ESHIFT);
                *(__half2*)&Ch[(size_t)r0 * N + cc]       = __floats2half2_rn(e0, e1);
                *(__half2*)&Ch[(size_t)(r0 + 8) * N + cc] = __floats2half2_rn(e2, e3);
                rs0 += e0 + e1;
                rs1 += e2 + e3;
            } else {
                float* Cp = Cext + (size_t)bz * sC;
                const float* rp = resExt + (size_t)bz * sRes;
                float2 ra = *(const float2*)&rp[(size_t)r0 * N + cc];
                float2 rb = *(const float2*)&rp[(size_t)(r0 + 8) * N + cc];
                *(float2*)&Cp[(size_t)r0 * N + cc] =
                    make_float2(v0 + b0f + ra.x, v1 + b0f + ra.y);
                *(float2*)&Cp[(size_t)(r0 + 8) * N + cc] =
                    make_float2(v2 + b1f + rb.x, v3 + b1f + rb.y);
            }
        }
        if (mode == 1) {
            // reduce the 4 lanes of each quad (same rows, different cols)
            rs0 += __shfl_xor_sync(0xffffffffu, rs0, 1);
            rs0 += __shfl_xor_sync(0xffffffffu, rs0, 2);
            rs1 += __shfl_xor_sync(0xffffffffu, rs1, 1);
            rs1 += __shfl_xor_sync(0xffffffffu, rs1, 2);
            if ((lane & 3) == 0) {
                atomicAdd(&g_Z[(size_t)bz * Nn + r0], rs0);
                atomicAdd(&g_Z[(size_t)bz * Nn + r0 + 8], rs1);
            }
        }
    }
}

// ============================================================
// attn*V:  ao'[c][i] = (1/Z_i) * sum_j V[c][j] * E[i][j]
//   A = V [m=c][k=j] (non-trans), B = E [n=i][k=j] (non-trans)
//   4-stage x 32k, 2 subchunks/iter (R11 config).
// ============================================================
#define PLD 40
#define STG_V (2*128*PLD)
#define SMEM_V_BYTES (4*STG_V*2)

#define AV_LOAD(buf, kk) do {                                                  \
    uint32_t sv_ = smb + (uint32_t)((buf) * STG_V) * 2;                        \
    uint32_t sp_ = sv_ + (uint32_t)(128 * PLD) * 2;                            \
    int r_ = tid >> 2, q_ = tid & 3;                                           \
    CPA16(sv_ + (uint32_t)(r_ * PLD + q_ * 8) * 2,                             \
          Vp + (size_t)(bm + r_) * Nn + (kk) + q_ * 8);                        \
    CPA16(sv_ + (uint32_t)((r_ + 64) * PLD + q_ * 8) * 2,                      \
          Vp + (size_t)(bm + r_ + 64) * Nn + (kk) + q_ * 8);                   \
    CPA16(sp_ + (uint32_t)(r_ * PLD + q_ * 8) * 2,                             \
          Pp + (size_t)(bn + r_) * Nn + (kk) + q_ * 8);                        \
    CPA16(sp_ + (uint32_t)((r_ + 64) * PLD + q_ * 8) * 2,                      \
          Pp + (size_t)(bn + r_ + 64) * Nn + (kk) + q_ * 8);                   \
    CP_COMMIT();                                                               \
} while (0)

__global__ __launch_bounds__(256, 2) void gemm_av_h() {
    extern __shared__ __half sm[];
    uint32_t smb = (uint32_t)__cvta_generic_to_shared(sm);

    int bz = blockIdx.z;
    const __half* Vp = g_h + OFF_QKV16 + (size_t)bz * 3 * Cc * Nn + (size_t)2 * Cc * Nn;
    const __half* Pp = g_h + OFF_P16 + (size_t)bz * Nn * Nn;
    __half* Cp = g_h + OFF_AO16 + (size_t)bz * Cc * Nn;
    int bm = blockIdx.y * BM, bn = blockIdx.x * BN;
    int tid = threadIdx.x, lane = tid & 31, wid = tid >> 5;
    int wm = (wid & 1) * 64, wn = (wid >> 1) * 32;

    float acc[4][4][4];
    #pragma unroll
    for (int i = 0; i < 4; i++)
        #pragma unroll
        for (int j = 0; j < 4; j++)
            #pragma unroll
            for (int r = 0; r < 4; r++) acc[i][j][r] = 0.f;

    int vRow = ((lane >> 3) & 1) * 8 + (lane & 7);
    int vCol = (lane >> 4) * 8;
    int pRow = (lane >> 4) * 8 + (lane & 7);
    int pCol = ((lane >> 3) & 1) * 8;

    int steps = Nn / 32;
    AV_LOAD(0, 0); AV_LOAD(1, 32); AV_LOAD(2, 64);

    for (int it = 0; it < steps; it++) {
        CP_WAIT(2);
        __syncthreads();
        if (it + 3 < steps) { AV_LOAD((it + 3) & 3, (it + 3) * 32); }
        else                { CP_COMMIT(); }

        uint32_t sv = smb + (uint32_t)((it & 3) * STG_V) * 2;
        uint32_t sp = sv + (uint32_t)(128 * PLD) * 2;

        #pragma unroll
        for (int sc = 0; sc < 2; sc++) {
            uint32_t a[4][4], b[4][2];
            #pragma unroll
            for (int mt = 0; mt < 4; mt++) {
                uint32_t ad = sv + (uint32_t)((wm + mt * 16 + vRow) * PLD + sc * 16 + vCol) * 2;
                LDSM4N(a[mt], ad);
            }
            #pragma unroll
            for (int np = 0; np < 2; np++) {
                uint32_t pd = sp + (uint32_t)((wn + np * 16 + pRow) * PLD + sc * 16 + pCol) * 2;
                uint32_t rr[4];
                LDSM4N(rr, pd);
                b[np * 2][0] = rr[0]; b[np * 2][1] = rr[1];
                b[np * 2 + 1][0] = rr[2]; b[np * 2 + 1][1] = rr[3];
            }
            #pragma unroll
            for (int mt = 0; mt < 4; mt++)
                #pragma unroll
                for (int nt = 0; nt < 4; nt++)
                    MMA16(acc[mt][nt], a[mt], b[nt]);
        }
    }

    // per-column 1/Z (column index = token i)
    float zi[4][2];
    #pragma unroll
    for (int nt = 0; nt < 4; nt++) {
        int cc = bn + wn + nt * 8 + 2 * (lane & 3);
        zi[nt][0] = 1.0f / g_Z[(size_t)bz * Nn + cc];
        zi[nt][1] = 1.0f / g_Z[(size_t)bz * Nn + cc + 1];
    }

    #pragma unroll
    for (int mt = 0; mt < 4; mt++) {
        int r0 = bm + wm + mt * 16 + (lane >> 2);
        #pragma unroll
        for (int nt = 0; nt < 4; nt++) {
            int cc = bn + wn + nt * 8 + 2 * (lane & 3);
            *(__half2*)&Cp[(size_t)r0 * Nn + cc] =
                __floats2half2_rn(acc[mt][nt][0] * zi[nt][0],
                                  acc[mt][nt][1] * zi[nt][1]);
            *(__half2*)&Cp[(size_t)(r0 + 8) * Nn + cc] =
                __floats2half2_rn(acc[mt][nt][2] * zi[nt][0],
                                  acc[mt][nt][3] * zi[nt][1]);
        }
    }
}

// ============================================================
extern "C" void kernel_launch(void* const* d_in, const int* in_sizes, int n_in,
                              void* d_out, int out_size) {
    const float* x     = (const float*)d_in[0];
    const float* gamma = (const float*)d_in[1];
    const float* beta  = (const float*)d_in[2];
    const float* qkv_w = (const float*)d_in[3];
    const float* qkv_b = (const float*)d_in[4];
    const float* out_w = (const float*)d_in[5];
    const float* out_b = (const float*)d_in[6];
    float* out = (float*)d_out;

    static bool attr_set = false;
    if (!attr_set) {
        cudaFuncSetAttribute(gemm_h, cudaFuncAttributeMaxDynamicSharedMemorySize,
                             SMEM_H_BYTES);
        cudaFuncSetAttribute(gemm_av_h, cudaFuncAttributeMaxDynamicSharedMemorySize,
                             SMEM_V_BYTES);
        attr_set = true;
    }

    zero_kernel<<<64, 256>>>();
    gn_part<<<Bb * Gg * 8, 256>>>(x);
    gn_apply<<<4096, 256>>>(x, gamma, beta);

    tr_f2h<<<dim3(Cc / 32, 3 * Cc / 32), dim3(32, 8)>>>(qkv_w, OFF_WQ16, 3 * Cc, Cc);
    tr_f2h<<<dim3(Cc / 32, Cc / 32), dim3(32, 8)>>>(out_w, OFF_WO16, Cc, Cc);

    // qkv16 = Wq16 * xn16 + b    (M=768, N=4096, K=256)
    gemm_h<<<dim3(Nn / BN, 3 * Cc / BM, Bb), 256, SMEM_H_BYTES>>>(
        OFF_WQ16, OFF_XN16, OFF_QKV16, nullptr,
        3 * Cc, Nn, Cc,
        0, (size_t)Cc * Nn, (size_t)3 * Cc * Nn,
        qkv_b, nullptr, 0, 1.0f, 0);

    // E = exp(Q^T K /16 - 4), row sums Z via atomics   (M=N=4096, K=256)
    gemm_h<<<dim3(Nn / BN, Nn / BM, Bb), 256, SMEM_H_BYTES>>>(
        OFF_QKV16, OFF_QKV16 + (size_t)Cc * Nn, OFF_P16, nullptr,
        Nn, Nn, Cc,
        (size_t)3 * Cc * Nn, (size_t)3 * Cc * Nn, (size_t)Nn * Nn,
        nullptr, nullptr, 0, 0.0625f, 1);

    // ao16 = (V * E^T) / Z     (M=256, N=4096, K=4096)
    gemm_av_h<<<dim3(Nn / BN, Cc / BM, Bb), 256, SMEM_V_BYTES>>>();

    // out = Wo16 * ao16 + b + x   (M=256, N=4096, K=256) -> fp32 ext
    gemm_h<<<dim3(Nn / BN, Cc / BM, Bb), 256, SMEM_H_BYTES>>>(
        OFF_WO16, OFF_AO16, 0, out,
        Cc, Nn, Cc,
        0, (size_t)Cc * Nn, (size_t)Cc * Nn,
        out_b, x, (size_t)Cc * Nn, 1.0f, 2);
}